// round 13
// baseline (speedup 1.0000x reference)
#include <cuda_runtime.h>
#include <cuda_bf16.h>
#include <math.h>
#include <stdint.h>

#define SEQ   2048
#define HID   2048
#define NH    16
#define NKV   4
#define HD    128
#define INTER 8192
#define QKVN  3072

#define MEGAF (1u << 20)
// fp32 scratch: qkv[0,6M) x[6M,10M) gu[10M,42M)
__device__ __align__(256) float g_f32[42u * MEGAF];
// bf16 (hi|lo): hA[0,8M) wqkvB[8M,20M) ctxA[20M,28M) woB[28M,36M)
// h2A[36M,44M) guB[44M,108M) siluA[108M,140M) wdB[140M,172M)
__device__ __align__(256) __nv_bfloat16 g_bf16[172u * MEGAF];

// ---------------------------------------------------------------------------
// cp.async helper
// ---------------------------------------------------------------------------
__device__ __forceinline__ void cp16(uint32_t dst, const void* src) {
    asm volatile("cp.async.cg.shared.global [%0], [%1], 16;\n"
                 :: "r"(dst), "l"(src));
}

// ---------------------------------------------------------------------------
// Tensor-core GEMM, bf16 hi/lo split (K' = 3K).
// 128x256 CTA tile, 8 warps (2x4) of 64x64. BK'=64, 256 threads.
// R11-proven pipeline: issue(next) -> commit -> wait 1 -> sync -> compute -> sync.
// Per warp/k-tile: 16 A-ldsm.x4 + 16 B-ldsm.x4 feed 128 mma (2x fewer ldsm/mma
// than the 128x128 config). smem: 2 stages x (16KB A + 32KB B) = 96KB.
// Grid: x = M tiles (fastest -> B-panel L2 reuse), y = N/256 tiles.
// ---------------------------------------------------------------------------
#define GEMM_SMEM 98304

__global__ __launch_bounds__(256) void gemm_bf16s(
    const __nv_bfloat16* __restrict__ A2,
    const __nv_bfloat16* __restrict__ B2,
    const float* __restrict__ res, float* __restrict__ C,
    int M, int N, int K) {
    extern __shared__ __nv_bfloat16 sm[];
    const int tid = threadIdx.x;
    const int lane = tid & 31, wid = tid >> 5;
    const int wm = wid >> 2, wn = wid & 3;          // 2x4 warps, 64x64 each
    const int rb = blockIdx.x * 128, cb = blockIdx.y * 256;
    const int K2 = 2 * K;
    const int T = (3 * K) / 64;
    const uint32_t smbase = (uint32_t)__cvta_generic_to_shared(sm);
    // stage s at smbase + s*49152: A [0,16K), B [16K,48K)
    float acc[4][8][4] = {};

    auto issue = [&](int it, int s) {
        int kk0 = it * 64;
        int ka0 = (kk0 < K2) ? kk0 : kk0 - K2;   // [Ah, Al, Ah]
        int kb0 = (kk0 < K)  ? kk0 : kk0 - K;    // [Bh, Bh, Bl]
        const __nv_bfloat16* Ab = A2 + (size_t)rb * K2 + ka0;
        const __nv_bfloat16* Bb = B2 + (size_t)cb * K2 + kb0;
        uint32_t sa = smbase + s * 49152;
        uint32_t sb = sa + 16384;
        #pragma unroll
        for (int i = 0; i < 4; i++) {            // A: 128 rows x 8 chunks
            int c = tid + i * 256;
            int row = c >> 3, col = c & 7;
            int sw = col ^ (row & 7);
            cp16(sa + (row * 64 + sw * 8) * 2, Ab + (size_t)row * K2 + col * 8);
        }
        #pragma unroll
        for (int i = 0; i < 8; i++) {            // B: 256 rows x 8 chunks
            int c = tid + i * 256;
            int row = c >> 3, col = c & 7;
            int sw = col ^ (row & 7);
            cp16(sb + (row * 64 + sw * 8) * 2, Bb + (size_t)row * K2 + col * 8);
        }
    };

    auto compute = [&](int s) {
        uint32_t sa = smbase + s * 49152;
        uint32_t sb = sa + 16384;
        #pragma unroll
        for (int ks = 0; ks < 4; ks++) {
            uint32_t af[4][4], bf[4][4];
            #pragma unroll
            for (int mt = 0; mt < 4; mt++) {
                int sub = lane >> 3;
                int r = wm * 64 + mt * 16 + (lane & 7) + (sub & 1) * 8;
                int cc = ks * 2 + (sub >> 1);
                uint32_t addr = sa + (r * 64 + ((cc ^ (r & 7)) * 8)) * 2;
                asm volatile(
                    "ldmatrix.sync.aligned.m8n8.x4.shared.b16 {%0,%1,%2,%3},[%4];"
                    : "=r"(af[mt][0]), "=r"(af[mt][1]),
                      "=r"(af[mt][2]), "=r"(af[mt][3]) : "r"(addr));
            }
            // B: 4 x ldsm.x4; matrices = {n[0:8) k-lo, n[8:16) k-lo,
            //                             n[0:8) k-hi, n[8:16) k-hi}
            #pragma unroll
            for (int p = 0; p < 4; p++) {
                int r = wn * 64 + p * 16 + (lane & 7) + ((lane >> 3) & 1) * 8;
                int cc = ks * 2 + (lane >> 4);
                uint32_t addr = sb + (r * 64 + ((cc ^ (r & 7)) * 8)) * 2;
                asm volatile(
                    "ldmatrix.sync.aligned.m8n8.x4.shared.b16 {%0,%1,%2,%3},[%4];"
                    : "=r"(bf[p][0]), "=r"(bf[p][1]),
                      "=r"(bf[p][2]), "=r"(bf[p][3]) : "r"(addr));
            }
            #pragma unroll
            for (int mt = 0; mt < 4; mt++)
                #pragma unroll
                for (int p = 0; p < 4; p++) {
                    asm volatile(
                        "mma.sync.aligned.m16n8k16.row.col.f32.bf16.bf16.f32 "
                        "{%0,%1,%2,%3},{%4,%5,%6,%7},{%8,%9},{%0,%1,%2,%3};"
                        : "+f"(acc[mt][2*p][0]), "+f"(acc[mt][2*p][1]),
                          "+f"(acc[mt][2*p][2]), "+f"(acc[mt][2*p][3])
                        : "r"(af[mt][0]), "r"(af[mt][1]),
                          "r"(af[mt][2]), "r"(af[mt][3]),
                          "r"(bf[p][0]), "r"(bf[p][2]));
                    asm volatile(
                        "mma.sync.aligned.m16n8k16.row.col.f32.bf16.bf16.f32 "
                        "{%0,%1,%2,%3},{%4,%5,%6,%7},{%8,%9},{%0,%1,%2,%3};"
                        : "+f"(acc[mt][2*p+1][0]), "+f"(acc[mt][2*p+1][1]),
                          "+f"(acc[mt][2*p+1][2]), "+f"(acc[mt][2*p+1][3])
                        : "r"(af[mt][0]), "r"(af[mt][1]),
                          "r"(af[mt][2]), "r"(af[mt][3]),
                          "r"(bf[p][1]), "r"(bf[p][3]));
                }
        }
    };

    issue(0, 0);
    asm volatile("cp.async.commit_group;");
    for (int it = 0; it < T; ++it) {
        if (it + 1 < T) {
            issue(it + 1, (it + 1) & 1);
            asm volatile("cp.async.commit_group;");
            asm volatile("cp.async.wait_group 1;");
        } else {
            asm volatile("cp.async.wait_group 0;");
        }
        __syncthreads();
        compute(it & 1);
        __syncthreads();
    }

    #pragma unroll
    for (int mt = 0; mt < 4; mt++) {
        int r0 = rb + wm * 64 + mt * 16 + (lane >> 2);
        #pragma unroll
        for (int nt = 0; nt < 8; nt++) {
            int col = cb + wn * 64 + nt * 8 + (lane & 3) * 2;
            float2 v0 = { acc[mt][nt][0], acc[mt][nt][1] };
            float2 v1 = { acc[mt][nt][2], acc[mt][nt][3] };
            if (res) {
                float2 a0 = *(const float2*)(res + (size_t)r0 * N + col);
                float2 a1 = *(const float2*)(res + (size_t)(r0 + 8) * N + col);
                v0.x += a0.x; v0.y += a0.y; v1.x += a1.x; v1.y += a1.y;
            }
            *(float2*)(C + (size_t)r0 * N + col) = v0;
            *(float2*)(C + (size_t)(r0 + 8) * N + col) = v1;
        }
    }
}

// ---------------------------------------------------------------------------
// RMSNorm fused with bf16 hi/lo split: out[row][2K] = [hi | lo].
// ---------------------------------------------------------------------------
__global__ __launch_bounds__(256) void rmsnorm_split_kernel(
    const float* __restrict__ x, const float* __restrict__ w,
    __nv_bfloat16* __restrict__ out) {
    int row = blockIdx.x;
    const float* xr = x + (size_t)row * HID;
    float s = 0.f;
    for (int i = threadIdx.x; i < HID / 4; i += blockDim.x) {
        float4 v = ((const float4*)xr)[i];
        s += v.x * v.x + v.y * v.y + v.z * v.z + v.w * v.w;
    }
    __shared__ float red[32];
    #pragma unroll
    for (int o = 16; o; o >>= 1) s += __shfl_xor_sync(0xffffffffu, s, o);
    int warp = threadIdx.x >> 5, lane = threadIdx.x & 31;
    if (lane == 0) red[warp] = s;
    __syncthreads();
    if (warp == 0) {
        s = (lane < (int)(blockDim.x >> 5)) ? red[lane] : 0.f;
        #pragma unroll
        for (int o = 16; o; o >>= 1) s += __shfl_xor_sync(0xffffffffu, s, o);
        if (lane == 0) red[0] = rsqrtf(s * (1.0f / HID) + 1e-6f);
    }
    __syncthreads();
    float r = red[0];
    __nv_bfloat16* orow = out + (size_t)row * 2 * HID;
    for (int i = threadIdx.x; i < HID / 4; i += blockDim.x) {
        float4 v = ((const float4*)xr)[i];
        float4 ww = ((const float4*)w)[i];
        float fv[4] = { v.x * r * ww.x, v.y * r * ww.y, v.z * r * ww.z, v.w * r * ww.w };
        __nv_bfloat16 hi[4], lo[4];
        #pragma unroll
        for (int j = 0; j < 4; j++) {
            hi[j] = __float2bfloat16(fv[j]);
            lo[j] = __float2bfloat16(fv[j] - __bfloat162float(hi[j]));
        }
        *(uint2*)(orow + i * 4)       = *(uint2*)hi;
        *(uint2*)(orow + HID + i * 4) = *(uint2*)lo;
    }
}

// ---------------------------------------------------------------------------
// Vectorized split fp32 [R][K] -> bf16 [R][2K]. 4 elem/thread.
// ---------------------------------------------------------------------------
__global__ __launch_bounds__(256) void split_kernel4(
    const float4* __restrict__ in, __nv_bfloat16* __restrict__ out,
    int total4, int kshift, int K) {
    int i = blockIdx.x * blockDim.x + threadIdx.x;
    if (i >= total4) return;
    int r  = i >> kshift;
    int c4 = i & ((1 << kshift) - 1);
    float4 v = in[i];
    float fv[4] = { v.x, v.y, v.z, v.w };
    __nv_bfloat16 hi[4], lo[4];
    #pragma unroll
    for (int j = 0; j < 4; j++) {
        hi[j] = __float2bfloat16(fv[j]);
        lo[j] = __float2bfloat16(fv[j] - __bfloat162float(hi[j]));
    }
    __nv_bfloat16* orow = out + (size_t)r * 2 * K;
    *(uint2*)(orow + c4 * 4)     = *(uint2*)hi;
    *(uint2*)(orow + K + c4 * 4) = *(uint2*)lo;
}

// ---------------------------------------------------------------------------
// RoPE (in place on fused qkv).
// ---------------------------------------------------------------------------
__global__ __launch_bounds__(256) void rope_kernel(
    float* __restrict__ x, int nh, int stride, int col0,
    const int* __restrict__ pos) {
    int idx = blockIdx.x * blockDim.x + threadIdx.x;
    int total = SEQ * nh * 64;
    if (idx >= total) return;
    int j = idx & 63;
    int t = idx >> 6;
    int hh = t % nh;
    int ss = t / nh;
    float invf = powf(10000.0f, -(float)j * (1.0f / 64.0f));
    float ang = (float)pos[ss] * invf;
    float sn, cs;
    sincosf(ang, &sn, &cs);
    float* base = x + (size_t)ss * stride + col0 + hh * HD + j;
    float x1 = base[0];
    float x2 = base[64];
    base[0]  = x1 * cs - x2 * sn;
    base[64] = x2 * cs + x1 * sn;
}

// ---------------------------------------------------------------------------
// Causal GQA attention, flash-style, fp32 SIMT with float4 phase A.
// qb reversed (heaviest CTAs first). Epilogue writes hi/lo bf16 into ctxA.
// ---------------------------------------------------------------------------
#define ATTN_SMEM ((32 * 128 + 32 * 132 + 32 * 128 + 32 * 33) * 4)

__global__ __launch_bounds__(128) void attn_kernel(
    const float* __restrict__ qkv, __nv_bfloat16* __restrict__ ctxA) {
    extern __shared__ float smf[];
    float* Qs = smf;
    float* Ks = Qs + 32 * 128;
    float* Vs = Ks + 32 * 132;
    float* Ps = Vs + 32 * 128;

    int head = blockIdx.y;
    int qb = (SEQ / 32 - 1) - blockIdx.x;     // reversed schedule
    int kvh = head >> 2;
    int tid = threadIdx.x;
    int lane = tid & 31, w = tid >> 5;
    int qbase = qb * 32;

    #pragma unroll
    for (int i = 0; i < 8; i++) {
        int l = tid + i * 128;
        int r = l >> 5, f4 = l & 31;
        float4 qq = *(const float4*)(qkv + (size_t)(qbase + r) * QKVN + head * HD + f4 * 4);
        *(float4*)(Qs + r * 128 + f4 * 4) = qq;
    }

    float m[8], lsum[8], acc[8][4];
    #pragma unroll
    for (int i = 0; i < 8; i++) {
        m[i] = -1e30f; lsum[i] = 0.f;
        acc[i][0] = acc[i][1] = acc[i][2] = acc[i][3] = 0.f;
    }

    for (int kt = 0; kt <= qb; kt++) {
        __syncthreads();
        #pragma unroll
        for (int i = 0; i < 8; i++) {
            int l = tid + i * 128;
            int key = l >> 5, f4 = l & 31;
            int d = f4 * 4;
            size_t gbase = (size_t)(kt * 32 + key) * QKVN + kvh * HD + d;
            float4 kk = *(const float4*)(qkv + gbase + 2048);
            *(float4*)(Ks + key * 132 + d) = kk;
            float4 vv = *(const float4*)(qkv + gbase + 2560);
            *(float4*)(Vs + key * 128 + d) = vv;
        }
        __syncthreads();

        float s[8];
        #pragma unroll
        for (int i = 0; i < 8; i++) s[i] = 0.f;
        const float* qrow = Qs + (w * 8) * 128;
        const float* krow = Ks + lane * 132;
        #pragma unroll 8
        for (int d0 = 0; d0 < 128; d0 += 4) {
            float4 kv = *(const float4*)(krow + d0);
            #pragma unroll
            for (int i = 0; i < 8; i++) {
                float4 qv = *(const float4*)(qrow + i * 128 + d0);
                s[i] += qv.x * kv.x + qv.y * kv.y + qv.z * kv.z + qv.w * kv.w;
            }
        }

        int key = kt * 32 + lane;
        #pragma unroll
        for (int i = 0; i < 8; i++) {
            int row = qbase + w * 8 + i;
            float sv = (key <= row) ? s[i] * 0.08838834764831845f : -1e30f;
            float mx = sv;
            #pragma unroll
            for (int o = 16; o; o >>= 1) mx = fmaxf(mx, __shfl_xor_sync(0xffffffffu, mx, o));
            float mnew = fmaxf(m[i], mx);
            float alpha = __expf(m[i] - mnew);
            float p = __expf(sv - mnew);
            float ps = p;
            #pragma unroll
            for (int o = 16; o; o >>= 1) ps += __shfl_xor_sync(0xffffffffu, ps, o);
            lsum[i] = lsum[i] * alpha + ps;
            m[i] = mnew;
            acc[i][0] *= alpha; acc[i][1] *= alpha;
            acc[i][2] *= alpha; acc[i][3] *= alpha;
            Ps[(w * 8 + i) * 33 + lane] = p;
        }
        __syncwarp();

        #pragma unroll 4
        for (int j = 0; j < 32; j++) {
            float4 vv = *(const float4*)(Vs + j * 128 + lane * 4);
            #pragma unroll
            for (int i = 0; i < 8; i++) {
                float pj = Ps[(w * 8 + i) * 33 + j];
                acc[i][0] += pj * vv.x;
                acc[i][1] += pj * vv.y;
                acc[i][2] += pj * vv.z;
                acc[i][3] += pj * vv.w;
            }
        }
    }

    #pragma unroll
    for (int i = 0; i < 8; i++) {
        float inv = 1.f / lsum[i];
        int row = qbase + w * 8 + i;
        float fv[4] = { acc[i][0] * inv, acc[i][1] * inv,
                        acc[i][2] * inv, acc[i][3] * inv };
        __nv_bfloat16 hi[4], lo[4];
        #pragma unroll
        for (int q = 0; q < 4; q++) {
            hi[q] = __float2bfloat16(fv[q]);
            lo[q] = __float2bfloat16(fv[q] - __bfloat162float(hi[q]));
        }
        __nv_bfloat16* orow = ctxA + (size_t)row * 2 * HID + head * HD + lane * 4;
        *(uint2*)(orow)       = *(uint2*)hi;
        *(uint2*)(orow + HID) = *(uint2*)lo;
    }
}

// ---------------------------------------------------------------------------
// SiLU(gate)*up fused with hi/lo split: gu [SEQ][16384] -> [SEQ][2*INTER].
// ---------------------------------------------------------------------------
__global__ __launch_bounds__(256) void silu_split_kernel(
    const float* __restrict__ gu, __nv_bfloat16* __restrict__ out) {
    int i = blockIdx.x * blockDim.x + threadIdx.x;
    if (i >= SEQ * (INTER / 4)) return;
    int r = i >> 11;
    int j = i & 2047;
    float4 gv = ((const float4*)(gu + (size_t)r * 16384))[j];
    float4 uv = ((const float4*)(gu + (size_t)r * 16384 + 8192))[j];
    float fv[4];
    fv[0] = gv.x / (1.f + __expf(-gv.x)) * uv.x;
    fv[1] = gv.y / (1.f + __expf(-gv.y)) * uv.y;
    fv[2] = gv.z / (1.f + __expf(-gv.z)) * uv.z;
    fv[3] = gv.w / (1.f + __expf(-gv.w)) * uv.w;
    __nv_bfloat16 hi[4], lo[4];
    #pragma unroll
    for (int q = 0; q < 4; q++) {
        hi[q] = __float2bfloat16(fv[q]);
        lo[q] = __float2bfloat16(fv[q] - __bfloat162float(hi[q]));
    }
    __nv_bfloat16* orow = out + (size_t)r * 2 * INTER;
    *(uint2*)(orow + j * 4)         = *(uint2*)hi;
    *(uint2*)(orow + INTER + j * 4) = *(uint2*)lo;
}

// ---------------------------------------------------------------------------
// Host side
// ---------------------------------------------------------------------------
static void gemm(const __nv_bfloat16* A2, const __nv_bfloat16* B2,
                 const float* res, float* C, int M, int N, int K) {
    dim3 grid(M / 128, N / 256);   // x = M fastest
    gemm_bf16s<<<grid, 256, GEMM_SMEM>>>(A2, B2, res, C, M, N, K);
}

static void split(const float* in, __nv_bfloat16* out, int R, int K) {
    int total4 = (int)(((size_t)R * K) >> 2);
    int kshift = (K == 2048) ? 9 : 11;   // log2(K/4)
    split_kernel4<<<(total4 + 255) / 256, 256>>>(
        (const float4*)in, out, total4, kshift, K);
}

extern "C" void kernel_launch(void* const* d_in, const int* in_sizes, int n_in,
                              void* d_out, int out_size) {
    const float* hidden = (const float*)d_in[0];
    const int*   pos    = (const int*)d_in[2];
    const float* n1     = (const float*)d_in[3];
    const float* n2     = (const float*)d_in[4];
    const float* Wq     = (const float*)d_in[5];
    const float* Wk     = (const float*)d_in[6];
    const float* Wv     = (const float*)d_in[7];
    const float* Wo     = (const float*)d_in[8];
    const float* Wg     = (const float*)d_in[9];
    const float* Wu     = (const float*)d_in[10];
    const float* Wd     = (const float*)d_in[11];
    float* out = (float*)d_out;

    float* f = nullptr;
    __nv_bfloat16* b = nullptr;
    cudaGetSymbolAddress((void**)&f, g_f32);
    cudaGetSymbolAddress((void**)&b, g_bf16);

    float* qkv  = f;
    float* x    = f + (size_t)6  * MEGAF;
    float* gu   = f + (size_t)10 * MEGAF;

    __nv_bfloat16* hA    = b;
    __nv_bfloat16* wqkvB = b + (size_t)8   * MEGAF;
    __nv_bfloat16* ctxA  = b + (size_t)20  * MEGAF;
    __nv_bfloat16* woB   = b + (size_t)28  * MEGAF;
    __nv_bfloat16* h2A   = b + (size_t)36  * MEGAF;
    __nv_bfloat16* guB   = b + (size_t)44  * MEGAF;
    __nv_bfloat16* siluA = b + (size_t)108 * MEGAF;
    __nv_bfloat16* wdB   = b + (size_t)140 * MEGAF;

    static bool attr_done = false;
    if (!attr_done) {
        cudaFuncSetAttribute(attn_kernel,
                             cudaFuncAttributeMaxDynamicSharedMemorySize, ATTN_SMEM);
        cudaFuncSetAttribute(gemm_bf16s,
                             cudaFuncAttributeMaxDynamicSharedMemorySize, GEMM_SMEM);
        attr_done = true;
    }

    // 1. RMSNorm 1 (fused hi/lo split)
    rmsnorm_split_kernel<<<SEQ, 256>>>(hidden, n1, hA);
    // 2. Split fused QKV weights: rows [Wq | Wk | Wv]
    split(Wq, wqkvB, 2048, HID);
    split(Wk, wqkvB + (size_t)2048 * 4096, 512, HID);
    split(Wv, wqkvB + (size_t)2560 * 4096, 512, HID);
    // 3. Fused QKV projection
    gemm(hA, wqkvB, nullptr, qkv, SEQ, QKVN, HID);
    // 4. RoPE
    rope_kernel<<<(SEQ * NH * 64 + 255) / 256, 256>>>(qkv, NH, QKVN, 0, pos);
    rope_kernel<<<(SEQ * NKV * 64 + 255) / 256, 256>>>(qkv, NKV, QKVN, 2048, pos);
    // 5. Attention (writes ctxA hi/lo directly)
    attn_kernel<<<dim3(SEQ / 32, NH), 128, ATTN_SMEM>>>(qkv, ctxA);
    // 6. O projection + residual
    split(Wo, woB, HID, HID);
    gemm(ctxA, woB, hidden, x, SEQ, HID, HID);
    // 7. RMSNorm 2 (fused hi/lo split)
    rmsnorm_split_kernel<<<SEQ, 256>>>(x, n2, h2A);
    // 8. Fused gate/up projection
    split(Wg, guB, INTER, HID);
    split(Wu, guB + (size_t)INTER * 4096, INTER, HID);
    gemm(h2A, guB, nullptr, gu, SEQ, 2 * INTER, HID);
    // 9. SiLU * up (fused hi/lo split)
    silu_split_kernel<<<(SEQ * (INTER / 4) + 255) / 256, 256>>>(gu, siluA);
    // 10. Down projection + residual -> output
    split(Wd, wdB, HID, INTER);
    gemm(siluA, wdB, x, out, SEQ, HID, INTER);
}

// round 14
// speedup vs baseline: 1.3856x; 1.3856x over previous
#include <cuda_runtime.h>
#include <cuda_fp16.h>
#include <math.h>
#include <stdint.h>

#define SEQ   2048
#define HID   2048
#define NH    16
#define NKV   4
#define HD    128
#define INTER 8192
#define QKVN  3072

#define MEGAF (1u << 20)
// fp32 scratch: qkv[0,6M) x[6M,10M) gu[10M,42M)
__device__ __align__(256) float g_f32[42u * MEGAF];
// fp16 (hi|lo): hA[0,8M) wqkvB[8M,20M) ctxA[20M,28M) woB[28M,36M)
// h2A[36M,44M) guB[44M,108M) siluA[108M,140M) wdB[140M,172M)
__device__ __align__(256) __half g_f16[172u * MEGAF];

// ---------------------------------------------------------------------------
// cp.async helper
// ---------------------------------------------------------------------------
__device__ __forceinline__ void cp16(uint32_t dst, const void* src) {
    asm volatile("cp.async.cg.shared.global [%0], [%1], 16;\n"
                 :: "r"(dst), "l"(src));
}

// ---------------------------------------------------------------------------
// Tensor-core GEMM, fp16 hi/lo split. SL = slices (3: AhBh+AlBh+AhBl exact
// to 2^-22; 2: (Ah+Al)Bh, B rounded to 2^-11). A2/B2 are [.][2K] hi|lo fp16.
// R11-proven config: 128x128 tile, BK'=64, 256 threads (8 warps, 2x4),
// cp.async double buffer, issue(next)->commit->wait->sync->compute->sync.
// Grid: x = M tiles (fastest -> B-panel L2 reuse), y = N tiles.
// ---------------------------------------------------------------------------
#define GEMM_SMEM 65536

__global__ __launch_bounds__(256) void gemm_f16s(
    const __half* __restrict__ A2,
    const __half* __restrict__ B2,
    const float* __restrict__ res, float* __restrict__ C,
    int M, int N, int K, int SL) {
    extern __shared__ __half sm[];
    const int tid = threadIdx.x;
    const int lane = tid & 31, wid = tid >> 5;
    const int wm = wid >> 2, wn = wid & 3;
    const int rb = blockIdx.x * 128, cb = blockIdx.y * 128;   // M-fastest
    const int K2 = 2 * K;
    const int T = (SL * K) / 64;
    const uint32_t smbase = (uint32_t)__cvta_generic_to_shared(sm);
    float acc[4][4][4] = {};

    auto issue = [&](int it, int s) {
        int kk0 = it * 64;
        int ka0 = (kk0 < K2) ? kk0 : kk0 - K2;   // SL=3: [Ah,Al,Ah]; SL=2: [Ah,Al]
        int kb0 = (kk0 < K)  ? kk0 : kk0 - K;    // SL=3: [Bh,Bh,Bl]; SL=2: [Bh,Bh]
        const __half* Ab = A2 + (size_t)rb * K2 + ka0;
        const __half* Bb = B2 + (size_t)cb * K2 + kb0;
        uint32_t sa = smbase + s * 16384;
        uint32_t sb = smbase + 32768 + s * 16384;
        #pragma unroll
        for (int i = 0; i < 4; i++) {
            int c = tid + i * 256;
            int row = c >> 3, col = c & 7;
            int sw = col ^ (row & 7);
            cp16(sa + (row * 64 + sw * 8) * 2, Ab + (size_t)row * K2 + col * 8);
            cp16(sb + (row * 64 + sw * 8) * 2, Bb + (size_t)row * K2 + col * 8);
        }
    };

    auto compute = [&](int s) {
        uint32_t sa = smbase + s * 16384;
        uint32_t sb = smbase + 32768 + s * 16384;
        #pragma unroll
        for (int ks = 0; ks < 4; ks++) {
            uint32_t af[4][4], bf[4][2];
            #pragma unroll
            for (int mt = 0; mt < 4; mt++) {
                int sub = lane >> 3;
                int r = wm * 64 + mt * 16 + (lane & 7) + (sub & 1) * 8;
                int cc = ks * 2 + (sub >> 1);
                uint32_t addr = sa + (r * 64 + ((cc ^ (r & 7)) * 8)) * 2;
                asm volatile(
                    "ldmatrix.sync.aligned.m8n8.x4.shared.b16 {%0,%1,%2,%3},[%4];"
                    : "=r"(af[mt][0]), "=r"(af[mt][1]),
                      "=r"(af[mt][2]), "=r"(af[mt][3]) : "r"(addr));
            }
            #pragma unroll
            for (int nt = 0; nt < 4; nt++) {
                int sub = (lane >> 3) & 1;
                int r = wn * 32 + nt * 8 + (lane & 7);
                int cc = ks * 2 + sub;
                uint32_t addr = sb + (r * 64 + ((cc ^ (r & 7)) * 8)) * 2;
                asm volatile(
                    "ldmatrix.sync.aligned.m8n8.x2.shared.b16 {%0,%1},[%2];"
                    : "=r"(bf[nt][0]), "=r"(bf[nt][1]) : "r"(addr));
            }
            #pragma unroll
            for (int mt = 0; mt < 4; mt++)
                #pragma unroll
                for (int nt = 0; nt < 4; nt++)
                    asm volatile(
                        "mma.sync.aligned.m16n8k16.row.col.f32.f16.f16.f32 "
                        "{%0,%1,%2,%3},{%4,%5,%6,%7},{%8,%9},{%0,%1,%2,%3};"
                        : "+f"(acc[mt][nt][0]), "+f"(acc[mt][nt][1]),
                          "+f"(acc[mt][nt][2]), "+f"(acc[mt][nt][3])
                        : "r"(af[mt][0]), "r"(af[mt][1]),
                          "r"(af[mt][2]), "r"(af[mt][3]),
                          "r"(bf[nt][0]), "r"(bf[nt][1]));
        }
    };

    issue(0, 0);
    asm volatile("cp.async.commit_group;");
    for (int it = 0; it < T; ++it) {
        if (it + 1 < T) {
            issue(it + 1, (it + 1) & 1);
            asm volatile("cp.async.commit_group;");
            asm volatile("cp.async.wait_group 1;");
        } else {
            asm volatile("cp.async.wait_group 0;");
        }
        __syncthreads();
        compute(it & 1);
        __syncthreads();
    }

    #pragma unroll
    for (int mt = 0; mt < 4; mt++) {
        int r0 = rb + wm * 64 + mt * 16 + (lane >> 2);
        #pragma unroll
        for (int nt = 0; nt < 4; nt++) {
            int col = cb + wn * 32 + nt * 8 + (lane & 3) * 2;
            float2 v0 = { acc[mt][nt][0], acc[mt][nt][1] };
            float2 v1 = { acc[mt][nt][2], acc[mt][nt][3] };
            if (res) {
                float2 a0 = *(const float2*)(res + (size_t)r0 * N + col);
                float2 a1 = *(const float2*)(res + (size_t)(r0 + 8) * N + col);
                v0.x += a0.x; v0.y += a0.y; v1.x += a1.x; v1.y += a1.y;
            }
            *(float2*)(C + (size_t)r0 * N + col) = v0;
            *(float2*)(C + (size_t)(r0 + 8) * N + col) = v1;
        }
    }
}

// ---------------------------------------------------------------------------
// RMSNorm fused with fp16 hi/lo split: out[row][2K] = [hi | lo].
// ---------------------------------------------------------------------------
__global__ __launch_bounds__(256) void rmsnorm_split_kernel(
    const float* __restrict__ x, const float* __restrict__ w,
    __half* __restrict__ out) {
    int row = blockIdx.x;
    const float* xr = x + (size_t)row * HID;
    float s = 0.f;
    for (int i = threadIdx.x; i < HID / 4; i += blockDim.x) {
        float4 v = ((const float4*)xr)[i];
        s += v.x * v.x + v.y * v.y + v.z * v.z + v.w * v.w;
    }
    __shared__ float red[32];
    #pragma unroll
    for (int o = 16; o; o >>= 1) s += __shfl_xor_sync(0xffffffffu, s, o);
    int warp = threadIdx.x >> 5, lane = threadIdx.x & 31;
    if (lane == 0) red[warp] = s;
    __syncthreads();
    if (warp == 0) {
        s = (lane < (int)(blockDim.x >> 5)) ? red[lane] : 0.f;
        #pragma unroll
        for (int o = 16; o; o >>= 1) s += __shfl_xor_sync(0xffffffffu, s, o);
        if (lane == 0) red[0] = rsqrtf(s * (1.0f / HID) + 1e-6f);
    }
    __syncthreads();
    float r = red[0];
    __half* orow = out + (size_t)row * 2 * HID;
    for (int i = threadIdx.x; i < HID / 4; i += blockDim.x) {
        float4 v = ((const float4*)xr)[i];
        float4 ww = ((const float4*)w)[i];
        float fv[4] = { v.x * r * ww.x, v.y * r * ww.y, v.z * r * ww.z, v.w * r * ww.w };
        __half hi[4], lo[4];
        #pragma unroll
        for (int j = 0; j < 4; j++) {
            hi[j] = __float2half(fv[j]);
            lo[j] = __float2half(fv[j] - __half2float(hi[j]));
        }
        *(uint2*)(orow + i * 4)       = *(uint2*)hi;
        *(uint2*)(orow + HID + i * 4) = *(uint2*)lo;
    }
}

// ---------------------------------------------------------------------------
// Vectorized split fp32 [R][K] -> fp16 [R][2K]. 4 elem/thread.
// ---------------------------------------------------------------------------
__global__ __launch_bounds__(256) void split_kernel4(
    const float4* __restrict__ in, __half* __restrict__ out,
    int total4, int kshift, int K) {
    int i = blockIdx.x * blockDim.x + threadIdx.x;
    if (i >= total4) return;
    int r  = i >> kshift;
    int c4 = i & ((1 << kshift) - 1);
    float4 v = in[i];
    float fv[4] = { v.x, v.y, v.z, v.w };
    __half hi[4], lo[4];
    #pragma unroll
    for (int j = 0; j < 4; j++) {
        hi[j] = __float2half(fv[j]);
        lo[j] = __float2half(fv[j] - __half2float(hi[j]));
    }
    __half* orow = out + (size_t)r * 2 * K;
    *(uint2*)(orow + c4 * 4)     = *(uint2*)hi;
    *(uint2*)(orow + K + c4 * 4) = *(uint2*)lo;
}

// ---------------------------------------------------------------------------
// RoPE (in place on fused qkv).
// ---------------------------------------------------------------------------
__global__ __launch_bounds__(256) void rope_kernel(
    float* __restrict__ x, int nh, int stride, int col0,
    const int* __restrict__ pos) {
    int idx = blockIdx.x * blockDim.x + threadIdx.x;
    int total = SEQ * nh * 64;
    if (idx >= total) return;
    int j = idx & 63;
    int t = idx >> 6;
    int hh = t % nh;
    int ss = t / nh;
    float invf = powf(10000.0f, -(float)j * (1.0f / 64.0f));
    float ang = (float)pos[ss] * invf;
    float sn, cs;
    sincosf(ang, &sn, &cs);
    float* base = x + (size_t)ss * stride + col0 + hh * HD + j;
    float x1 = base[0];
    float x2 = base[64];
    base[0]  = x1 * cs - x2 * sn;
    base[64] = x2 * cs + x1 * sn;
}

// ---------------------------------------------------------------------------
// Causal GQA attention, flash-style, fp32 SIMT with float4 phase A.
// qb reversed (heaviest CTAs first). Epilogue writes fp16 hi/lo into ctxA.
// ---------------------------------------------------------------------------
#define ATTN_SMEM ((32 * 128 + 32 * 132 + 32 * 128 + 32 * 33) * 4)

__global__ __launch_bounds__(128) void attn_kernel(
    const float* __restrict__ qkv, __half* __restrict__ ctxA) {
    extern __shared__ float smf[];
    float* Qs = smf;
    float* Ks = Qs + 32 * 128;
    float* Vs = Ks + 32 * 132;
    float* Ps = Vs + 32 * 128;

    int head = blockIdx.y;
    int qb = (SEQ / 32 - 1) - blockIdx.x;     // reversed schedule
    int kvh = head >> 2;
    int tid = threadIdx.x;
    int lane = tid & 31, w = tid >> 5;
    int qbase = qb * 32;

    #pragma unroll
    for (int i = 0; i < 8; i++) {
        int l = tid + i * 128;
        int r = l >> 5, f4 = l & 31;
        float4 qq = *(const float4*)(qkv + (size_t)(qbase + r) * QKVN + head * HD + f4 * 4);
        *(float4*)(Qs + r * 128 + f4 * 4) = qq;
    }

    float m[8], lsum[8], acc[8][4];
    #pragma unroll
    for (int i = 0; i < 8; i++) {
        m[i] = -1e30f; lsum[i] = 0.f;
        acc[i][0] = acc[i][1] = acc[i][2] = acc[i][3] = 0.f;
    }

    for (int kt = 0; kt <= qb; kt++) {
        __syncthreads();
        #pragma unroll
        for (int i = 0; i < 8; i++) {
            int l = tid + i * 128;
            int key = l >> 5, f4 = l & 31;
            int d = f4 * 4;
            size_t gbase = (size_t)(kt * 32 + key) * QKVN + kvh * HD + d;
            float4 kk = *(const float4*)(qkv + gbase + 2048);
            *(float4*)(Ks + key * 132 + d) = kk;
            float4 vv = *(const float4*)(qkv + gbase + 2560);
            *(float4*)(Vs + key * 128 + d) = vv;
        }
        __syncthreads();

        float s[8];
        #pragma unroll
        for (int i = 0; i < 8; i++) s[i] = 0.f;
        const float* qrow = Qs + (w * 8) * 128;
        const float* krow = Ks + lane * 132;
        #pragma unroll 8
        for (int d0 = 0; d0 < 128; d0 += 4) {
            float4 kv = *(const float4*)(krow + d0);
            #pragma unroll
            for (int i = 0; i < 8; i++) {
                float4 qv = *(const float4*)(qrow + i * 128 + d0);
                s[i] += qv.x * kv.x + qv.y * kv.y + qv.z * kv.z + qv.w * kv.w;
            }
        }

        int key = kt * 32 + lane;
        #pragma unroll
        for (int i = 0; i < 8; i++) {
            int row = qbase + w * 8 + i;
            float sv = (key <= row) ? s[i] * 0.08838834764831845f : -1e30f;
            float mx = sv;
            #pragma unroll
            for (int o = 16; o; o >>= 1) mx = fmaxf(mx, __shfl_xor_sync(0xffffffffu, mx, o));
            float mnew = fmaxf(m[i], mx);
            float alpha = __expf(m[i] - mnew);
            float p = __expf(sv - mnew);
            float ps = p;
            #pragma unroll
            for (int o = 16; o; o >>= 1) ps += __shfl_xor_sync(0xffffffffu, ps, o);
            lsum[i] = lsum[i] * alpha + ps;
            m[i] = mnew;
            acc[i][0] *= alpha; acc[i][1] *= alpha;
            acc[i][2] *= alpha; acc[i][3] *= alpha;
            Ps[(w * 8 + i) * 33 + lane] = p;
        }
        __syncwarp();

        #pragma unroll 4
        for (int j = 0; j < 32; j++) {
            float4 vv = *(const float4*)(Vs + j * 128 + lane * 4);
            #pragma unroll
            for (int i = 0; i < 8; i++) {
                float pj = Ps[(w * 8 + i) * 33 + j];
                acc[i][0] += pj * vv.x;
                acc[i][1] += pj * vv.y;
                acc[i][2] += pj * vv.z;
                acc[i][3] += pj * vv.w;
            }
        }
    }

    #pragma unroll
    for (int i = 0; i < 8; i++) {
        float inv = 1.f / lsum[i];
        int row = qbase + w * 8 + i;
        float fv[4] = { acc[i][0] * inv, acc[i][1] * inv,
                        acc[i][2] * inv, acc[i][3] * inv };
        __half hi[4], lo[4];
        #pragma unroll
        for (int q = 0; q < 4; q++) {
            hi[q] = __float2half(fv[q]);
            lo[q] = __float2half(fv[q] - __half2float(hi[q]));
        }
        __half* orow = ctxA + (size_t)row * 2 * HID + head * HD + lane * 4;
        *(uint2*)(orow)       = *(uint2*)hi;
        *(uint2*)(orow + HID) = *(uint2*)lo;
    }
}

// ---------------------------------------------------------------------------
// SiLU(gate)*up fused with fp16 hi/lo split: gu [SEQ][16384] -> [SEQ][2*INTER].
// ---------------------------------------------------------------------------
__global__ __launch_bounds__(256) void silu_split_kernel(
    const float* __restrict__ gu, __half* __restrict__ out) {
    int i = blockIdx.x * blockDim.x + threadIdx.x;
    if (i >= SEQ * (INTER / 4)) return;
    int r = i >> 11;
    int j = i & 2047;
    float4 gv = ((const float4*)(gu + (size_t)r * 16384))[j];
    float4 uv = ((const float4*)(gu + (size_t)r * 16384 + 8192))[j];
    float fv[4];
    fv[0] = gv.x / (1.f + __expf(-gv.x)) * uv.x;
    fv[1] = gv.y / (1.f + __expf(-gv.y)) * uv.y;
    fv[2] = gv.z / (1.f + __expf(-gv.z)) * uv.z;
    fv[3] = gv.w / (1.f + __expf(-gv.w)) * uv.w;
    __half hi[4], lo[4];
    #pragma unroll
    for (int q = 0; q < 4; q++) {
        hi[q] = __float2half(fv[q]);
        lo[q] = __float2half(fv[q] - __half2float(hi[q]));
    }
    __half* orow = out + (size_t)r * 2 * INTER;
    *(uint2*)(orow + j * 4)         = *(uint2*)hi;
    *(uint2*)(orow + INTER + j * 4) = *(uint2*)lo;
}

// ---------------------------------------------------------------------------
// Host side
// ---------------------------------------------------------------------------
static void gemm(const __half* A2, const __half* B2,
                 const float* res, float* C, int M, int N, int K, int SL) {
    dim3 grid(M / 128, N / 128);   // x = M fastest
    gemm_f16s<<<grid, 256, GEMM_SMEM>>>(A2, B2, res, C, M, N, K, SL);
}

static void split(const float* in, __half* out, int R, int K) {
    int total4 = (int)(((size_t)R * K) >> 2);
    int kshift = (K == 2048) ? 9 : 11;   // log2(K/4)
    split_kernel4<<<(total4 + 255) / 256, 256>>>(
        (const float4*)in, out, total4, kshift, K);
}

extern "C" void kernel_launch(void* const* d_in, const int* in_sizes, int n_in,
                              void* d_out, int out_size) {
    const float* hidden = (const float*)d_in[0];
    const int*   pos    = (const int*)d_in[2];
    const float* n1     = (const float*)d_in[3];
    const float* n2     = (const float*)d_in[4];
    const float* Wq     = (const float*)d_in[5];
    const float* Wk     = (const float*)d_in[6];
    const float* Wv     = (const float*)d_in[7];
    const float* Wo     = (const float*)d_in[8];
    const float* Wg     = (const float*)d_in[9];
    const float* Wu     = (const float*)d_in[10];
    const float* Wd     = (const float*)d_in[11];
    float* out = (float*)d_out;

    float* f = nullptr;
    __half* b = nullptr;
    cudaGetSymbolAddress((void**)&f, g_f32);
    cudaGetSymbolAddress((void**)&b, g_f16);

    float* qkv  = f;
    float* x    = f + (size_t)6  * MEGAF;
    float* gu   = f + (size_t)10 * MEGAF;

    __half* hA    = b;
    __half* wqkvB = b + (size_t)8   * MEGAF;
    __half* ctxA  = b + (size_t)20  * MEGAF;
    __half* woB   = b + (size_t)28  * MEGAF;
    __half* h2A   = b + (size_t)36  * MEGAF;
    __half* guB   = b + (size_t)44  * MEGAF;
    __half* siluA = b + (size_t)108 * MEGAF;
    __half* wdB   = b + (size_t)140 * MEGAF;

    static bool attr_done = false;
    if (!attr_done) {
        cudaFuncSetAttribute(attn_kernel,
                             cudaFuncAttributeMaxDynamicSharedMemorySize, ATTN_SMEM);
        cudaFuncSetAttribute(gemm_f16s,
                             cudaFuncAttributeMaxDynamicSharedMemorySize, GEMM_SMEM);
        attr_done = true;
    }

    // 1. RMSNorm 1 (fused hi/lo split)
    rmsnorm_split_kernel<<<SEQ, 256>>>(hidden, n1, hA);
    // 2. Split fused QKV weights: rows [Wq | Wk | Wv]
    split(Wq, wqkvB, 2048, HID);
    split(Wk, wqkvB + (size_t)2048 * 4096, 512, HID);
    split(Wv, wqkvB + (size_t)2560 * 4096, 512, HID);
    // 3. Fused QKV projection (3-slice: attention path stays high-precision)
    gemm(hA, wqkvB, nullptr, qkv, SEQ, QKVN, HID, 3);
    // 4. RoPE
    rope_kernel<<<(SEQ * NH * 64 + 255) / 256, 256>>>(qkv, NH, QKVN, 0, pos);
    rope_kernel<<<(SEQ * NKV * 64 + 255) / 256, 256>>>(qkv, NKV, QKVN, 2048, pos);
    // 5. Attention (writes ctxA hi/lo directly)
    attn_kernel<<<dim3(SEQ / 32, NH), 128, ATTN_SMEM>>>(qkv, ctxA);
    // 6. O projection + residual (3-slice)
    split(Wo, woB, HID, HID);
    gemm(ctxA, woB, hidden, x, SEQ, HID, HID, 3);
    // 7. RMSNorm 2 (fused hi/lo split)
    rmsnorm_split_kernel<<<SEQ, 256>>>(x, n2, h2A);
    // 8. Fused gate/up projection (2-slice fp16)
    split(Wg, guB, INTER, HID);
    split(Wu, guB + (size_t)INTER * 4096, INTER, HID);
    gemm(h2A, guB, nullptr, gu, SEQ, 2 * INTER, HID, 2);
    // 9. SiLU * up (fused hi/lo split)
    silu_split_kernel<<<(SEQ * (INTER / 4) + 255) / 256, 256>>>(gu, siluA);
    // 10. Down projection + residual -> output (2-slice fp16)
    split(Wd, wdB, HID, INTER);
    gemm(siluA, wdB, x, out, SEQ, HID, INTER, 2);
}

// round 16
// speedup vs baseline: 1.6741x; 1.2082x over previous
#include <cuda_runtime.h>
#include <cuda_fp16.h>
#include <math.h>
#include <stdint.h>

#define SEQ   2048
#define HID   2048
#define NH    16
#define NKV   4
#define HD    128
#define INTER 8192
#define QKVN  3072

#define MEGAF (1u << 20)
// fp32 scratch: qkv[0,6M) x[6M,10M) gu[10M,42M)
__device__ __align__(256) float g_f32[42u * MEGAF];
// fp16 (hi|lo): hA[0,8M) wqkvB[8M,20M) ctxA[20M,28M) woB[28M,36M)
// h2A[36M,44M) guB[44M,108M) siluA[108M,140M) wdB[140M,172M)
__device__ __align__(256) __half g_f16[172u * MEGAF];

// ---------------------------------------------------------------------------
// helpers
// ---------------------------------------------------------------------------
__device__ __forceinline__ void cp16(uint32_t dst, const void* src) {
    asm volatile("cp.async.cg.shared.global [%0], [%1], 16;\n"
                 :: "r"(dst), "l"(src));
}

// split pair of floats -> hi half2 bits, lo half2 bits
__device__ __forceinline__ void split2(float a, float b,
                                       uint32_t& hi, uint32_t& lo) {
    __half2 h = __floats2half2_rn(a, b);
    float2 hf = __half22float2(h);
    __half2 l = __floats2half2_rn(a - hf.x, b - hf.y);
    hi = *(uint32_t*)&h;
    lo = *(uint32_t*)&l;
}

// ---------------------------------------------------------------------------
// Tensor-core GEMM, fp16 hi/lo split. SL slices (R14-proven).
// ---------------------------------------------------------------------------
#define GEMM_SMEM 65536

__global__ __launch_bounds__(256) void gemm_f16s(
    const __half* __restrict__ A2,
    const __half* __restrict__ B2,
    const float* __restrict__ res, float* __restrict__ C,
    int M, int N, int K, int SL) {
    extern __shared__ __half sm[];
    const int tid = threadIdx.x;
    const int lane = tid & 31, wid = tid >> 5;
    const int wm = wid >> 2, wn = wid & 3;
    const int rb = blockIdx.x * 128, cb = blockIdx.y * 128;
    const int K2 = 2 * K;
    const int T = (SL * K) / 64;
    const uint32_t smbase = (uint32_t)__cvta_generic_to_shared(sm);
    float acc[4][4][4] = {};

    auto issue = [&](int it, int s) {
        int kk0 = it * 64;
        int ka0 = (kk0 < K2) ? kk0 : kk0 - K2;
        int kb0 = (kk0 < K)  ? kk0 : kk0 - K;
        const __half* Ab = A2 + (size_t)rb * K2 + ka0;
        const __half* Bb = B2 + (size_t)cb * K2 + kb0;
        uint32_t sa = smbase + s * 16384;
        uint32_t sb = smbase + 32768 + s * 16384;
        #pragma unroll
        for (int i = 0; i < 4; i++) {
            int c = tid + i * 256;
            int row = c >> 3, col = c & 7;
            int sw = col ^ (row & 7);
            cp16(sa + (row * 64 + sw * 8) * 2, Ab + (size_t)row * K2 + col * 8);
            cp16(sb + (row * 64 + sw * 8) * 2, Bb + (size_t)row * K2 + col * 8);
        }
    };

    auto compute = [&](int s) {
        uint32_t sa = smbase + s * 16384;
        uint32_t sb = smbase + 32768 + s * 16384;
        #pragma unroll
        for (int ks = 0; ks < 4; ks++) {
            uint32_t af[4][4], bf[4][2];
            #pragma unroll
            for (int mt = 0; mt < 4; mt++) {
                int sub = lane >> 3;
                int r = wm * 64 + mt * 16 + (lane & 7) + (sub & 1) * 8;
                int cc = ks * 2 + (sub >> 1);
                uint32_t addr = sa + (r * 64 + ((cc ^ (r & 7)) * 8)) * 2;
                asm volatile(
                    "ldmatrix.sync.aligned.m8n8.x4.shared.b16 {%0,%1,%2,%3},[%4];"
                    : "=r"(af[mt][0]), "=r"(af[mt][1]),
                      "=r"(af[mt][2]), "=r"(af[mt][3]) : "r"(addr));
            }
            #pragma unroll
            for (int nt = 0; nt < 4; nt++) {
                int sub = (lane >> 3) & 1;
                int r = wn * 32 + nt * 8 + (lane & 7);
                int cc = ks * 2 + sub;
                uint32_t addr = sb + (r * 64 + ((cc ^ (r & 7)) * 8)) * 2;
                asm volatile(
                    "ldmatrix.sync.aligned.m8n8.x2.shared.b16 {%0,%1},[%2];"
                    : "=r"(bf[nt][0]), "=r"(bf[nt][1]) : "r"(addr));
            }
            #pragma unroll
            for (int mt = 0; mt < 4; mt++)
                #pragma unroll
                for (int nt = 0; nt < 4; nt++)
                    asm volatile(
                        "mma.sync.aligned.m16n8k16.row.col.f32.f16.f16.f32 "
                        "{%0,%1,%2,%3},{%4,%5,%6,%7},{%8,%9},{%0,%1,%2,%3};"
                        : "+f"(acc[mt][nt][0]), "+f"(acc[mt][nt][1]),
                          "+f"(acc[mt][nt][2]), "+f"(acc[mt][nt][3])
                        : "r"(af[mt][0]), "r"(af[mt][1]),
                          "r"(af[mt][2]), "r"(af[mt][3]),
                          "r"(bf[nt][0]), "r"(bf[nt][1]));
        }
    };

    issue(0, 0);
    asm volatile("cp.async.commit_group;");
    for (int it = 0; it < T; ++it) {
        if (it + 1 < T) {
            issue(it + 1, (it + 1) & 1);
            asm volatile("cp.async.commit_group;");
            asm volatile("cp.async.wait_group 1;");
        } else {
            asm volatile("cp.async.wait_group 0;");
        }
        __syncthreads();
        compute(it & 1);
        __syncthreads();
    }

    #pragma unroll
    for (int mt = 0; mt < 4; mt++) {
        int r0 = rb + wm * 64 + mt * 16 + (lane >> 2);
        #pragma unroll
        for (int nt = 0; nt < 4; nt++) {
            int col = cb + wn * 32 + nt * 8 + (lane & 3) * 2;
            float2 v0 = { acc[mt][nt][0], acc[mt][nt][1] };
            float2 v1 = { acc[mt][nt][2], acc[mt][nt][3] };
            if (res) {
                float2 a0 = *(const float2*)(res + (size_t)r0 * N + col);
                float2 a1 = *(const float2*)(res + (size_t)(r0 + 8) * N + col);
                v0.x += a0.x; v0.y += a0.y; v1.x += a1.x; v1.y += a1.y;
            }
            *(float2*)(C + (size_t)r0 * N + col) = v0;
            *(float2*)(C + (size_t)(r0 + 8) * N + col) = v1;
        }
    }
}

// ---------------------------------------------------------------------------
// RMSNorm fused with fp16 hi/lo split.
// ---------------------------------------------------------------------------
__global__ __launch_bounds__(256) void rmsnorm_split_kernel(
    const float* __restrict__ x, const float* __restrict__ w,
    __half* __restrict__ out) {
    int row = blockIdx.x;
    const float* xr = x + (size_t)row * HID;
    float s = 0.f;
    for (int i = threadIdx.x; i < HID / 4; i += blockDim.x) {
        float4 v = ((const float4*)xr)[i];
        s += v.x * v.x + v.y * v.y + v.z * v.z + v.w * v.w;
    }
    __shared__ float red[32];
    #pragma unroll
    for (int o = 16; o; o >>= 1) s += __shfl_xor_sync(0xffffffffu, s, o);
    int warp = threadIdx.x >> 5, lane = threadIdx.x & 31;
    if (lane == 0) red[warp] = s;
    __syncthreads();
    if (warp == 0) {
        s = (lane < (int)(blockDim.x >> 5)) ? red[lane] : 0.f;
        #pragma unroll
        for (int o = 16; o; o >>= 1) s += __shfl_xor_sync(0xffffffffu, s, o);
        if (lane == 0) red[0] = rsqrtf(s * (1.0f / HID) + 1e-6f);
    }
    __syncthreads();
    float r = red[0];
    __half* orow = out + (size_t)row * 2 * HID;
    for (int i = threadIdx.x; i < HID / 4; i += blockDim.x) {
        float4 v = ((const float4*)xr)[i];
        float4 ww = ((const float4*)w)[i];
        uint32_t h0, l0, h1, l1;
        split2(v.x * r * ww.x, v.y * r * ww.y, h0, l0);
        split2(v.z * r * ww.z, v.w * r * ww.w, h1, l1);
        *(uint2*)(orow + i * 4)       = make_uint2(h0, h1);
        *(uint2*)(orow + HID + i * 4) = make_uint2(l0, l1);
    }
}

// ---------------------------------------------------------------------------
// Vectorized split fp32 [R][K] -> fp16 [R][2K].
// ---------------------------------------------------------------------------
__global__ __launch_bounds__(256) void split_kernel4(
    const float4* __restrict__ in, __half* __restrict__ out,
    int total4, int kshift, int K) {
    int i = blockIdx.x * blockDim.x + threadIdx.x;
    if (i >= total4) return;
    int r  = i >> kshift;
    int c4 = i & ((1 << kshift) - 1);
    float4 v = in[i];
    uint32_t h0, l0, h1, l1;
    split2(v.x, v.y, h0, l0);
    split2(v.z, v.w, h1, l1);
    __half* orow = out + (size_t)r * 2 * K;
    *(uint2*)(orow + c4 * 4)     = make_uint2(h0, h1);
    *(uint2*)(orow + K + c4 * 4) = make_uint2(l0, l1);
}

// ---------------------------------------------------------------------------
// RoPE (in place on fused qkv).
// ---------------------------------------------------------------------------
__global__ __launch_bounds__(256) void rope_kernel(
    float* __restrict__ x, int nh, int stride, int col0,
    const int* __restrict__ pos) {
    int idx = blockIdx.x * blockDim.x + threadIdx.x;
    int total = SEQ * nh * 64;
    if (idx >= total) return;
    int j = idx & 63;
    int t = idx >> 6;
    int hh = t % nh;
    int ss = t / nh;
    float invf = powf(10000.0f, -(float)j * (1.0f / 64.0f));
    float ang = (float)pos[ss] * invf;
    float sn, cs;
    sincosf(ang, &sn, &cs);
    float* base = x + (size_t)ss * stride + col0 + hh * HD + j;
    float x1 = base[0];
    float x2 = base[64];
    base[0]  = x1 * cs - x2 * sn;
    base[64] = x2 * cs + x1 * sn;
}

// ---------------------------------------------------------------------------
// Tensor-core causal GQA attention.
// CTA = 64 queries x 1 head, 128 threads (4 warps; warp = 16 query rows).
// QK^T: 3-slice fp16 (logits exact); PV: (Ph+Pl) x Vh (P exact, V fp16).
// Output written as fp16 hi/lo into ctxA [row][2*HID].
// smem halves: QH[0,8192) QL[8192,16384) KH[16384,20480) KL[20480,24576)
//              VT[24576,29696) PW[29696,34816)   -> 69632 bytes.
// ---------------------------------------------------------------------------
#define QH_OFF 0
#define QL_OFF 8192
#define KH_OFF 16384
#define KL_OFF 20480
#define VT_OFF 24576
#define PW_OFF 29696
#define ATTN_SMEM (34816 * 2)

__global__ __launch_bounds__(128) void attn_tc_kernel(
    const float* __restrict__ qkv, __half* __restrict__ ctxA) {
    extern __shared__ __half sma[];
    const uint32_t smb = (uint32_t)__cvta_generic_to_shared(sma);
    const int head = blockIdx.y;
    const int qb = 31 - blockIdx.x;            // reversed schedule
    const int qbase = qb * 64;
    const int kvh = head >> 2;
    const int tid = threadIdx.x;
    const int lane = tid & 31, w = tid >> 5;

    // ---- load Q (64 x 128) as hi/lo swizzled A-tiles ----
    #pragma unroll
    for (int i = 0; i < 16; i++) {
        int idx = tid + i * 128;               // 2048 float4 slots
        int row = idx >> 5;
        int d = (idx & 31) * 4;
        float4 qv = *(const float4*)(qkv + (size_t)(qbase + row) * QKVN +
                                     head * HD + d);
        uint32_t h0, l0, h1, l1;
        split2(qv.x, qv.y, h0, l0);
        split2(qv.z, qv.w, h1, l1);
        int tile = d >> 6, dd = d & 63;
        int chunk = dd >> 3, off = dd & 7;
        int base = tile * 4096 + row * 64 + ((chunk ^ (row & 7)) * 8) + off;
        *(uint2*)(sma + QH_OFF + base) = make_uint2(h0, h1);
        *(uint2*)(sma + QL_OFF + base) = make_uint2(l0, l1);
    }

    float m[2] = { -1e30f, -1e30f };
    float l[2] = { 0.f, 0.f };
    float acc_o[16][4] = {};
    const int r0 = lane >> 2;
    const int n_kt = 2 * qb + 2;

    for (int kt = 0; kt < n_kt; kt++) {
        __syncthreads();
        // ---- load K (hi/lo swizzled B-tiles) and V (transposed, hi) ----
        #pragma unroll
        for (int i = 0; i < 8; i++) {
            int idx = tid + i * 128;           // 1024 float4 slots
            int key = idx >> 5;
            int d = (idx & 31) * 4;
            size_t gbase = (size_t)(kt * 32 + key) * QKVN + kvh * HD + d;
            float4 kk = *(const float4*)(qkv + gbase + 2048);
            uint32_t h0, l0, h1, l1;
            split2(kk.x, kk.y, h0, l0);
            split2(kk.z, kk.w, h1, l1);
            int tile = d >> 6, dd = d & 63;
            int chunk = dd >> 3, off = dd & 7;
            int base = tile * 2048 + key * 64 + ((chunk ^ (key & 7)) * 8) + off;
            *(uint2*)(sma + KH_OFF + base) = make_uint2(h0, h1);
            *(uint2*)(sma + KL_OFF + base) = make_uint2(l0, l1);
            float4 vv = *(const float4*)(qkv + gbase + 2560);
            sma[VT_OFF + (d + 0) * 40 + key] = __float2half_rn(vv.x);
            sma[VT_OFF + (d + 1) * 40 + key] = __float2half_rn(vv.y);
            sma[VT_OFF + (d + 2) * 40 + key] = __float2half_rn(vv.z);
            sma[VT_OFF + (d + 3) * 40 + key] = __float2half_rn(vv.w);
        }
        __syncthreads();

        // warp fully masked for this tile?
        if (kt * 32 > qbase + w * 16 + 15) continue;

        // ---- QK^T, 3 slices ----
        float s[4][4] = {};
        const int aoff[3] = { QH_OFF, QL_OFF, QH_OFF };
        const int boff[3] = { KH_OFF, KH_OFF, KL_OFF };
        #pragma unroll
        for (int p = 0; p < 3; p++) {
            #pragma unroll
            for (int kh = 0; kh < 2; kh++) {
                #pragma unroll
                for (int ks = 0; ks < 4; ks++) {
                    uint32_t a0, a1, a2, a3;
                    {
                        int sub = lane >> 3;
                        int r = w * 16 + (lane & 7) + (sub & 1) * 8;
                        int cc = ks * 2 + (sub >> 1);
                        uint32_t addr = smb + (uint32_t)(aoff[p] + kh * 4096 +
                            r * 64 + ((cc ^ (r & 7)) * 8)) * 2;
                        asm volatile(
                            "ldmatrix.sync.aligned.m8n8.x4.shared.b16 "
                            "{%0,%1,%2,%3},[%4];"
                            : "=r"(a0), "=r"(a1), "=r"(a2), "=r"(a3)
                            : "r"(addr));
                    }
                    #pragma unroll
                    for (int nt = 0; nt < 4; nt++) {
                        uint32_t b0, b1;
                        int r2 = nt * 8 + (lane & 7);
                        int cc2 = ks * 2 + ((lane >> 3) & 1);
                        uint32_t addr = smb + (uint32_t)(boff[p] + kh * 2048 +
                            r2 * 64 + ((cc2 ^ (r2 & 7)) * 8)) * 2;
                        asm volatile(
                            "ldmatrix.sync.aligned.m8n8.x2.shared.b16 "
                            "{%0,%1},[%2];"
                            : "=r"(b0), "=r"(b1) : "r"(addr));
                        asm volatile(
                            "mma.sync.aligned.m16n8k16.row.col.f32.f16.f16.f32 "
                            "{%0,%1,%2,%3},{%4,%5,%6,%7},{%8,%9},{%0,%1,%2,%3};"
                            : "+f"(s[nt][0]), "+f"(s[nt][1]),
                              "+f"(s[nt][2]), "+f"(s[nt][3])
                            : "r"(a0), "r"(a1), "r"(a2), "r"(a3),
                              "r"(b0), "r"(b1));
                    }
                }
            }
        }

        // ---- online softmax (per row pair r0, r0+8) ----
        float alpha[2];
        __half* pw = sma + PW_OFF + w * 1280;
        #pragma unroll
        for (int i = 0; i < 2; i++) {
            int row = qbase + w * 16 + r0 + i * 8;
            float mx = -1e30f;
            #pragma unroll
            for (int nt = 0; nt < 4; nt++)
                #pragma unroll
                for (int j = 0; j < 2; j++) {
                    int key = kt * 32 + nt * 8 + (lane & 3) * 2 + j;
                    float sv = (key <= row)
                        ? s[nt][i * 2 + j] * 0.08838834764831845f : -1e30f;
                    s[nt][i * 2 + j] = sv;
                    mx = fmaxf(mx, sv);
                }
            mx = fmaxf(mx, __shfl_xor_sync(0xffffffffu, mx, 1));
            mx = fmaxf(mx, __shfl_xor_sync(0xffffffffu, mx, 2));
            float mnew = fmaxf(m[i], mx);
            alpha[i] = __expf(m[i] - mnew);
            m[i] = mnew;
            float psum = 0.f;
            #pragma unroll
            for (int nt = 0; nt < 4; nt++) {
                float p0 = __expf(s[nt][i * 2 + 0] - mnew);
                float p1 = __expf(s[nt][i * 2 + 1] - mnew);
                psum += p0 + p1;
                uint32_t hb, lb;
                split2(p0, p1, hb, lb);
                int po = (r0 + i * 8) * 40 + nt * 8 + (lane & 3) * 2;
                *(uint32_t*)(pw + po)       = hb;   // Ph
                *(uint32_t*)(pw + 640 + po) = lb;   // Pl
            }
            psum += __shfl_xor_sync(0xffffffffu, psum, 1);
            psum += __shfl_xor_sync(0xffffffffu, psum, 2);
            l[i] = l[i] * alpha[i] + psum;
            #pragma unroll
            for (int nt = 0; nt < 16; nt++) {
                acc_o[nt][i * 2 + 0] *= alpha[i];
                acc_o[nt][i * 2 + 1] *= alpha[i];
            }
        }
        __syncwarp();

        // ---- PV: (Ph + Pl) x Vh ----
        #pragma unroll
        for (int sl = 0; sl < 2; sl++) {
            #pragma unroll
            for (int ks = 0; ks < 2; ks++) {
                uint32_t a0, a1, a2, a3;
                {
                    int sub = lane >> 3;
                    int r = (lane & 7) + (sub & 1) * 8;
                    uint32_t addr = smb + (uint32_t)(PW_OFF + w * 1280 +
                        sl * 640 + r * 40 + ks * 16 + (sub >> 1) * 8) * 2;
                    asm volatile(
                        "ldmatrix.sync.aligned.m8n8.x4.shared.b16 "
                        "{%0,%1,%2,%3},[%4];"
                        : "=r"(a0), "=r"(a1), "=r"(a2), "=r"(a3) : "r"(addr));
                }
                #pragma unroll
                for (int nt = 0; nt < 16; nt++) {
                    uint32_t b0, b1;
                    int rr = nt * 8 + (lane & 7);
                    uint32_t addr = smb + (uint32_t)(VT_OFF + rr * 40 +
                        ks * 16 + ((lane >> 3) & 1) * 8) * 2;
                    asm volatile(
                        "ldmatrix.sync.aligned.m8n8.x2.shared.b16 {%0,%1},[%2];"
                        : "=r"(b0), "=r"(b1) : "r"(addr));
                    asm volatile(
                        "mma.sync.aligned.m16n8k16.row.col.f32.f16.f16.f32 "
                        "{%0,%1,%2,%3},{%4,%5,%6,%7},{%8,%9},{%0,%1,%2,%3};"
                        : "+f"(acc_o[nt][0]), "+f"(acc_o[nt][1]),
                          "+f"(acc_o[nt][2]), "+f"(acc_o[nt][3])
                        : "r"(a0), "r"(a1), "r"(a2), "r"(a3),
                          "r"(b0), "r"(b1));
                }
            }
        }
    }

    // ---- normalize + write fp16 hi/lo into ctxA ----
    float inv[2] = { 1.f / l[0], 1.f / l[1] };
    #pragma unroll
    for (int nt = 0; nt < 16; nt++) {
        #pragma unroll
        for (int i = 0; i < 2; i++) {
            int row = qbase + w * 16 + r0 + i * 8;
            float v0 = acc_o[nt][i * 2 + 0] * inv[i];
            float v1 = acc_o[nt][i * 2 + 1] * inv[i];
            uint32_t hb, lb;
            split2(v0, v1, hb, lb);
            __half* o = ctxA + (size_t)row * 2 * HID + head * HD +
                        nt * 8 + (lane & 3) * 2;
            *(uint32_t*)(o)       = hb;
            *(uint32_t*)(o + HID) = lb;
        }
    }
}

// ---------------------------------------------------------------------------
// SiLU(gate)*up fused with fp16 hi/lo split.
// ---------------------------------------------------------------------------
__global__ __launch_bounds__(256) void silu_split_kernel(
    const float* __restrict__ gu, __half* __restrict__ out) {
    int i = blockIdx.x * blockDim.x + threadIdx.x;
    if (i >= SEQ * (INTER / 4)) return;
    int r = i >> 11;
    int j = i & 2047;
    float4 gv = ((const float4*)(gu + (size_t)r * 16384))[j];
    float4 uv = ((const float4*)(gu + (size_t)r * 16384 + 8192))[j];
    float f0 = gv.x / (1.f + __expf(-gv.x)) * uv.x;
    float f1 = gv.y / (1.f + __expf(-gv.y)) * uv.y;
    float f2 = gv.z / (1.f + __expf(-gv.z)) * uv.z;
    float f3 = gv.w / (1.f + __expf(-gv.w)) * uv.w;
    uint32_t h0, l0, h1, l1;
    split2(f0, f1, h0, l0);
    split2(f2, f3, h1, l1);
    __half* orow = out + (size_t)r * 2 * INTER;
    *(uint2*)(orow + j * 4)         = make_uint2(h0, h1);
    *(uint2*)(orow + INTER + j * 4) = make_uint2(l0, l1);
}

// ---------------------------------------------------------------------------
// Host side
// ---------------------------------------------------------------------------
static void gemm(const __half* A2, const __half* B2,
                 const float* res, float* C, int M, int N, int K, int SL) {
    dim3 grid(M / 128, N / 128);
    gemm_f16s<<<grid, 256, GEMM_SMEM>>>(A2, B2, res, C, M, N, K, SL);
}

static void split(const float* in, __half* out, int R, int K) {
    int total4 = (int)(((size_t)R * K) >> 2);
    int kshift = (K == 2048) ? 9 : 11;
    split_kernel4<<<(total4 + 255) / 256, 256>>>(
        (const float4*)in, out, total4, kshift, K);
}

extern "C" void kernel_launch(void* const* d_in, const int* in_sizes, int n_in,
                              void* d_out, int out_size) {
    const float* hidden = (const float*)d_in[0];
    const int*   pos    = (const int*)d_in[2];
    const float* n1     = (const float*)d_in[3];
    const float* n2     = (const float*)d_in[4];
    const float* Wq     = (const float*)d_in[5];
    const float* Wk     = (const float*)d_in[6];
    const float* Wv     = (const float*)d_in[7];
    const float* Wo     = (const float*)d_in[8];
    const float* Wg     = (const float*)d_in[9];
    const float* Wu     = (const float*)d_in[10];
    const float* Wd     = (const float*)d_in[11];
    float* out = (float*)d_out;

    float* f = nullptr;
    __half* b = nullptr;
    cudaGetSymbolAddress((void**)&f, g_f32);
    cudaGetSymbolAddress((void**)&b, g_f16);

    float* qkv  = f;
    float* x    = f + (size_t)6  * MEGAF;
    float* gu   = f + (size_t)10 * MEGAF;

    __half* hA    = b;
    __half* wqkvB = b + (size_t)8   * MEGAF;
    __half* ctxA  = b + (size_t)20  * MEGAF;
    __half* woB   = b + (size_t)28  * MEGAF;
    __half* h2A   = b + (size_t)36  * MEGAF;
    __half* guB   = b + (size_t)44  * MEGAF;
    __half* siluA = b + (size_t)108 * MEGAF;
    __half* wdB   = b + (size_t)140 * MEGAF;

    static bool attr_done = false;
    if (!attr_done) {
        cudaFuncSetAttribute(attn_tc_kernel,
                             cudaFuncAttributeMaxDynamicSharedMemorySize, ATTN_SMEM);
        cudaFuncSetAttribute(gemm_f16s,
                             cudaFuncAttributeMaxDynamicSharedMemorySize, GEMM_SMEM);
        attr_done = true;
    }

    // 1. RMSNorm 1 (fused hi/lo split)
    rmsnorm_split_kernel<<<SEQ, 256>>>(hidden, n1, hA);
    // 2. Split fused QKV weights: rows [Wq | Wk | Wv]
    split(Wq, wqkvB, 2048, HID);
    split(Wk, wqkvB + (size_t)2048 * 4096, 512, HID);
    split(Wv, wqkvB + (size_t)2560 * 4096, 512, HID);
    // 3. Fused QKV projection (3-slice: precise q/k into attention)
    gemm(hA, wqkvB, nullptr, qkv, SEQ, QKVN, HID, 3);
    // 4. RoPE
    rope_kernel<<<(SEQ * NH * 64 + 255) / 256, 256>>>(qkv, NH, QKVN, 0, pos);
    rope_kernel<<<(SEQ * NKV * 64 + 255) / 256, 256>>>(qkv, NKV, QKVN, 2048, pos);
    // 5. Tensor-core attention (writes ctxA hi/lo directly)
    attn_tc_kernel<<<dim3(32, NH), 128, ATTN_SMEM>>>(qkv, ctxA);
    // 6. O projection + residual (3-slice)
    split(Wo, woB, HID, HID);
    gemm(ctxA, woB, hidden, x, SEQ, HID, HID, 3);
    // 7. RMSNorm 2 (fused hi/lo split)
    rmsnorm_split_kernel<<<SEQ, 256>>>(x, n2, h2A);
    // 8. Fused gate/up projection (2-slice)
    split(Wg, guB, INTER, HID);
    split(Wu, guB + (size_t)INTER * 4096, INTER, HID);
    gemm(h2A, guB, nullptr, gu, SEQ, 2 * INTER, HID, 2);
    // 9. SiLU * up (fused hi/lo split)
    silu_split_kernel<<<(SEQ * (INTER / 4) + 255) / 256, 256>>>(gu, siluA);
    // 10. Down projection + residual -> output (2-slice)
    split(Wd, wdB, HID, INTER);
    gemm(siluA, wdB, x, out, SEQ, HID, INTER, 2);
}

// round 17
// speedup vs baseline: 1.7128x; 1.0231x over previous
#include <cuda_runtime.h>
#include <cuda_fp16.h>
#include <math.h>
#include <stdint.h>

#define SEQ   2048
#define HID   2048
#define NH    16
#define NKV   4
#define HD    128
#define INTER 8192
#define QKVN  3072

#define MEGAF (1u << 20)
// fp32 scratch: qkv[0,6M) x[6M,10M)
__device__ __align__(256) float g_f32[10u * MEGAF];
// fp16 (hi|lo): hA[0,8M) wqkvB[8M,20M) ctxA[20M,28M) woB[28M,36M)
// h2A[36M,44M) guB[44M,108M) siluA[108M,140M) wdB[140M,172M)
__device__ __align__(256) __half g_f16[172u * MEGAF];

// ---------------------------------------------------------------------------
// helpers
// ---------------------------------------------------------------------------
__device__ __forceinline__ void cp16(uint32_t dst, const void* src) {
    asm volatile("cp.async.cg.shared.global [%0], [%1], 16;\n"
                 :: "r"(dst), "l"(src));
}

__device__ __forceinline__ void split2(float a, float b,
                                       uint32_t& hi, uint32_t& lo) {
    __half2 h = __floats2half2_rn(a, b);
    float2 hf = __half22float2(h);
    __half2 l = __floats2half2_rn(a - hf.x, b - hf.y);
    hi = *(uint32_t*)&h;
    lo = *(uint32_t*)&l;
}

// ---------------------------------------------------------------------------
// Tensor-core GEMM, fp16 hi/lo split, SL slices (R14-proven core).
// mode 0: C = A@B^T (+res), fp32 out.
// mode 1: gate/up interleaved epilogue — B rows alternate gate/up; output
//         silu(gate)*up written as fp16 hi/lo into Chalf [M][2*INTER].
// ---------------------------------------------------------------------------
#define GEMM_SMEM 65536

__global__ __launch_bounds__(256) void gemm_f16s(
    const __half* __restrict__ A2,
    const __half* __restrict__ B2,
    const float* __restrict__ res, float* __restrict__ C,
    __half* __restrict__ Chalf,
    int M, int N, int K, int SL, int mode) {
    extern __shared__ __half sm[];
    const int tid = threadIdx.x;
    const int lane = tid & 31, wid = tid >> 5;
    const int wm = wid >> 2, wn = wid & 3;
    const int rb = blockIdx.x * 128, cb = blockIdx.y * 128;
    const int K2 = 2 * K;
    const int T = (SL * K) / 64;
    const uint32_t smbase = (uint32_t)__cvta_generic_to_shared(sm);
    float acc[4][4][4] = {};

    auto issue = [&](int it, int s) {
        int kk0 = it * 64;
        int ka0 = (kk0 < K2) ? kk0 : kk0 - K2;
        int kb0 = (kk0 < K)  ? kk0 : kk0 - K;
        const __half* Ab = A2 + (size_t)rb * K2 + ka0;
        const __half* Bb = B2 + (size_t)cb * K2 + kb0;
        uint32_t sa = smbase + s * 16384;
        uint32_t sb = smbase + 32768 + s * 16384;
        #pragma unroll
        for (int i = 0; i < 4; i++) {
            int c = tid + i * 256;
            int row = c >> 3, col = c & 7;
            int sw = col ^ (row & 7);
            cp16(sa + (row * 64 + sw * 8) * 2, Ab + (size_t)row * K2 + col * 8);
            cp16(sb + (row * 64 + sw * 8) * 2, Bb + (size_t)row * K2 + col * 8);
        }
    };

    auto compute = [&](int s) {
        uint32_t sa = smbase + s * 16384;
        uint32_t sb = smbase + 32768 + s * 16384;
        #pragma unroll
        for (int ks = 0; ks < 4; ks++) {
            uint32_t af[4][4], bf[4][2];
            #pragma unroll
            for (int mt = 0; mt < 4; mt++) {
                int sub = lane >> 3;
                int r = wm * 64 + mt * 16 + (lane & 7) + (sub & 1) * 8;
                int cc = ks * 2 + (sub >> 1);
                uint32_t addr = sa + (r * 64 + ((cc ^ (r & 7)) * 8)) * 2;
                asm volatile(
                    "ldmatrix.sync.aligned.m8n8.x4.shared.b16 {%0,%1,%2,%3},[%4];"
                    : "=r"(af[mt][0]), "=r"(af[mt][1]),
                      "=r"(af[mt][2]), "=r"(af[mt][3]) : "r"(addr));
            }
            #pragma unroll
            for (int nt = 0; nt < 4; nt++) {
                int sub = (lane >> 3) & 1;
                int r = wn * 32 + nt * 8 + (lane & 7);
                int cc = ks * 2 + sub;
                uint32_t addr = sb + (r * 64 + ((cc ^ (r & 7)) * 8)) * 2;
                asm volatile(
                    "ldmatrix.sync.aligned.m8n8.x2.shared.b16 {%0,%1},[%2];"
                    : "=r"(bf[nt][0]), "=r"(bf[nt][1]) : "r"(addr));
            }
            #pragma unroll
            for (int mt = 0; mt < 4; mt++)
                #pragma unroll
                for (int nt = 0; nt < 4; nt++)
                    asm volatile(
                        "mma.sync.aligned.m16n8k16.row.col.f32.f16.f16.f32 "
                        "{%0,%1,%2,%3},{%4,%5,%6,%7},{%8,%9},{%0,%1,%2,%3};"
                        : "+f"(acc[mt][nt][0]), "+f"(acc[mt][nt][1]),
                          "+f"(acc[mt][nt][2]), "+f"(acc[mt][nt][3])
                        : "r"(af[mt][0]), "r"(af[mt][1]),
                          "r"(af[mt][2]), "r"(af[mt][3]),
                          "r"(bf[nt][0]), "r"(bf[nt][1]));
        }
    };

    issue(0, 0);
    asm volatile("cp.async.commit_group;");
    for (int it = 0; it < T; ++it) {
        if (it + 1 < T) {
            issue(it + 1, (it + 1) & 1);
            asm volatile("cp.async.commit_group;");
            asm volatile("cp.async.wait_group 1;");
        } else {
            asm volatile("cp.async.wait_group 0;");
        }
        __syncthreads();
        compute(it & 1);
        __syncthreads();
    }

    if (mode == 0) {
        #pragma unroll
        for (int mt = 0; mt < 4; mt++) {
            int r0 = rb + wm * 64 + mt * 16 + (lane >> 2);
            #pragma unroll
            for (int nt = 0; nt < 4; nt++) {
                int col = cb + wn * 32 + nt * 8 + (lane & 3) * 2;
                float2 v0 = { acc[mt][nt][0], acc[mt][nt][1] };
                float2 v1 = { acc[mt][nt][2], acc[mt][nt][3] };
                if (res) {
                    float2 a0 = *(const float2*)(res + (size_t)r0 * N + col);
                    float2 a1 = *(const float2*)(res + (size_t)(r0 + 8) * N + col);
                    v0.x += a0.x; v0.y += a0.y; v1.x += a1.x; v1.y += a1.y;
                }
                *(float2*)(C + (size_t)r0 * N + col) = v0;
                *(float2*)(C + (size_t)(r0 + 8) * N + col) = v1;
            }
        }
    } else {
        // silu-pair epilogue: cols (2j, 2j+1) = (gate_j, up_j)
        #pragma unroll
        for (int mt = 0; mt < 4; mt++) {
            int r0 = rb + wm * 64 + mt * 16 + (lane >> 2);
            #pragma unroll
            for (int nt = 0; nt < 4; nt++) {
                int j = (cb + wn * 32 + nt * 8 + (lane & 3) * 2) >> 1;
                float g0 = acc[mt][nt][0], u0 = acc[mt][nt][1];
                float g1 = acc[mt][nt][2], u1 = acc[mt][nt][3];
                float f0 = g0 / (1.f + __expf(-g0)) * u0;
                float f1 = g1 / (1.f + __expf(-g1)) * u1;
                __half h0 = __float2half_rn(f0);
                __half l0 = __float2half_rn(f0 - __half2float(h0));
                __half h1 = __float2half_rn(f1);
                __half l1 = __float2half_rn(f1 - __half2float(h1));
                __half* o0 = Chalf + (size_t)r0 * 2 * INTER + j;
                __half* o1 = Chalf + (size_t)(r0 + 8) * 2 * INTER + j;
                o0[0] = h0; o0[INTER] = l0;
                o1[0] = h1; o1[INTER] = l1;
            }
        }
    }
}

// ---------------------------------------------------------------------------
// RMSNorm fused with fp16 hi/lo split.
// ---------------------------------------------------------------------------
__global__ __launch_bounds__(256) void rmsnorm_split_kernel(
    const float* __restrict__ x, const float* __restrict__ w,
    __half* __restrict__ out) {
    int row = blockIdx.x;
    const float* xr = x + (size_t)row * HID;
    float s = 0.f;
    for (int i = threadIdx.x; i < HID / 4; i += blockDim.x) {
        float4 v = ((const float4*)xr)[i];
        s += v.x * v.x + v.y * v.y + v.z * v.z + v.w * v.w;
    }
    __shared__ float red[32];
    #pragma unroll
    for (int o = 16; o; o >>= 1) s += __shfl_xor_sync(0xffffffffu, s, o);
    int warp = threadIdx.x >> 5, lane = threadIdx.x & 31;
    if (lane == 0) red[warp] = s;
    __syncthreads();
    if (warp == 0) {
        s = (lane < (int)(blockDim.x >> 5)) ? red[lane] : 0.f;
        #pragma unroll
        for (int o = 16; o; o >>= 1) s += __shfl_xor_sync(0xffffffffu, s, o);
        if (lane == 0) red[0] = rsqrtf(s * (1.0f / HID) + 1e-6f);
    }
    __syncthreads();
    float r = red[0];
    __half* orow = out + (size_t)row * 2 * HID;
    for (int i = threadIdx.x; i < HID / 4; i += blockDim.x) {
        float4 v = ((const float4*)xr)[i];
        float4 ww = ((const float4*)w)[i];
        uint32_t h0, l0, h1, l1;
        split2(v.x * r * ww.x, v.y * r * ww.y, h0, l0);
        split2(v.z * r * ww.z, v.w * r * ww.w, h1, l1);
        *(uint2*)(orow + i * 4)       = make_uint2(h0, h1);
        *(uint2*)(orow + HID + i * 4) = make_uint2(l0, l1);
    }
}

// ---------------------------------------------------------------------------
// Vectorized split fp32 [R][K] -> fp16 [.][2K], output row = r*rowmul+rowoff.
// ---------------------------------------------------------------------------
__global__ __launch_bounds__(256) void split_kernel4(
    const float4* __restrict__ in, __half* __restrict__ out,
    int total4, int kshift, int K, int rowmul, int rowoff) {
    int i = blockIdx.x * blockDim.x + threadIdx.x;
    if (i >= total4) return;
    int r  = i >> kshift;
    int c4 = i & ((1 << kshift) - 1);
    float4 v = in[i];
    uint32_t h0, l0, h1, l1;
    split2(v.x, v.y, h0, l0);
    split2(v.z, v.w, h1, l1);
    __half* orow = out + (size_t)(r * rowmul + rowoff) * 2 * K;
    *(uint2*)(orow + c4 * 4)     = make_uint2(h0, h1);
    *(uint2*)(orow + K + c4 * 4) = make_uint2(l0, l1);
}

// ---------------------------------------------------------------------------
// RoPE (in place on fused qkv).
// ---------------------------------------------------------------------------
__global__ __launch_bounds__(256) void rope_kernel(
    float* __restrict__ x, int nh, int stride, int col0,
    const int* __restrict__ pos) {
    int idx = blockIdx.x * blockDim.x + threadIdx.x;
    int total = SEQ * nh * 64;
    if (idx >= total) return;
    int j = idx & 63;
    int t = idx >> 6;
    int hh = t % nh;
    int ss = t / nh;
    float invf = powf(10000.0f, -(float)j * (1.0f / 64.0f));
    float ang = (float)pos[ss] * invf;
    float sn, cs;
    sincosf(ang, &sn, &cs);
    float* base = x + (size_t)ss * stride + col0 + hh * HD + j;
    float x1 = base[0];
    float x2 = base[64];
    base[0]  = x1 * cs - x2 * sn;
    base[64] = x2 * cs + x1 * sn;
}

// ---------------------------------------------------------------------------
// Tensor-core causal GQA attention (R16-proven).
// ---------------------------------------------------------------------------
#define QH_OFF 0
#define QL_OFF 8192
#define KH_OFF 16384
#define KL_OFF 20480
#define VT_OFF 24576
#define PW_OFF 29696
#define ATTN_SMEM (34816 * 2)

__global__ __launch_bounds__(128) void attn_tc_kernel(
    const float* __restrict__ qkv, __half* __restrict__ ctxA) {
    extern __shared__ __half sma[];
    const uint32_t smb = (uint32_t)__cvta_generic_to_shared(sma);
    const int head = blockIdx.y;
    const int qb = 31 - blockIdx.x;
    const int qbase = qb * 64;
    const int kvh = head >> 2;
    const int tid = threadIdx.x;
    const int lane = tid & 31, w = tid >> 5;

    #pragma unroll
    for (int i = 0; i < 16; i++) {
        int idx = tid + i * 128;
        int row = idx >> 5;
        int d = (idx & 31) * 4;
        float4 qv = *(const float4*)(qkv + (size_t)(qbase + row) * QKVN +
                                     head * HD + d);
        uint32_t h0, l0, h1, l1;
        split2(qv.x, qv.y, h0, l0);
        split2(qv.z, qv.w, h1, l1);
        int tile = d >> 6, dd = d & 63;
        int chunk = dd >> 3, off = dd & 7;
        int base = tile * 4096 + row * 64 + ((chunk ^ (row & 7)) * 8) + off;
        *(uint2*)(sma + QH_OFF + base) = make_uint2(h0, h1);
        *(uint2*)(sma + QL_OFF + base) = make_uint2(l0, l1);
    }

    float m[2] = { -1e30f, -1e30f };
    float l[2] = { 0.f, 0.f };
    float acc_o[16][4] = {};
    const int r0 = lane >> 2;
    const int n_kt = 2 * qb + 2;

    for (int kt = 0; kt < n_kt; kt++) {
        __syncthreads();
        #pragma unroll
        for (int i = 0; i < 8; i++) {
            int idx = tid + i * 128;
            int key = idx >> 5;
            int d = (idx & 31) * 4;
            size_t gbase = (size_t)(kt * 32 + key) * QKVN + kvh * HD + d;
            float4 kk = *(const float4*)(qkv + gbase + 2048);
            uint32_t h0, l0, h1, l1;
            split2(kk.x, kk.y, h0, l0);
            split2(kk.z, kk.w, h1, l1);
            int tile = d >> 6, dd = d & 63;
            int chunk = dd >> 3, off = dd & 7;
            int base = tile * 2048 + key * 64 + ((chunk ^ (key & 7)) * 8) + off;
            *(uint2*)(sma + KH_OFF + base) = make_uint2(h0, h1);
            *(uint2*)(sma + KL_OFF + base) = make_uint2(l0, l1);
            float4 vv = *(const float4*)(qkv + gbase + 2560);
            sma[VT_OFF + (d + 0) * 40 + key] = __float2half_rn(vv.x);
            sma[VT_OFF + (d + 1) * 40 + key] = __float2half_rn(vv.y);
            sma[VT_OFF + (d + 2) * 40 + key] = __float2half_rn(vv.z);
            sma[VT_OFF + (d + 3) * 40 + key] = __float2half_rn(vv.w);
        }
        __syncthreads();

        if (kt * 32 > qbase + w * 16 + 15) continue;

        float s[4][4] = {};
        const int aoff[3] = { QH_OFF, QL_OFF, QH_OFF };
        const int boff[3] = { KH_OFF, KH_OFF, KL_OFF };
        #pragma unroll
        for (int p = 0; p < 3; p++) {
            #pragma unroll
            for (int kh = 0; kh < 2; kh++) {
                #pragma unroll
                for (int ks = 0; ks < 4; ks++) {
                    uint32_t a0, a1, a2, a3;
                    {
                        int sub = lane >> 3;
                        int r = w * 16 + (lane & 7) + (sub & 1) * 8;
                        int cc = ks * 2 + (sub >> 1);
                        uint32_t addr = smb + (uint32_t)(aoff[p] + kh * 4096 +
                            r * 64 + ((cc ^ (r & 7)) * 8)) * 2;
                        asm volatile(
                            "ldmatrix.sync.aligned.m8n8.x4.shared.b16 "
                            "{%0,%1,%2,%3},[%4];"
                            : "=r"(a0), "=r"(a1), "=r"(a2), "=r"(a3)
                            : "r"(addr));
                    }
                    #pragma unroll
                    for (int nt = 0; nt < 4; nt++) {
                        uint32_t b0, b1;
                        int r2 = nt * 8 + (lane & 7);
                        int cc2 = ks * 2 + ((lane >> 3) & 1);
                        uint32_t addr = smb + (uint32_t)(boff[p] + kh * 2048 +
                            r2 * 64 + ((cc2 ^ (r2 & 7)) * 8)) * 2;
                        asm volatile(
                            "ldmatrix.sync.aligned.m8n8.x2.shared.b16 "
                            "{%0,%1},[%2];"
                            : "=r"(b0), "=r"(b1) : "r"(addr));
                        asm volatile(
                            "mma.sync.aligned.m16n8k16.row.col.f32.f16.f16.f32 "
                            "{%0,%1,%2,%3},{%4,%5,%6,%7},{%8,%9},{%0,%1,%2,%3};"
                            : "+f"(s[nt][0]), "+f"(s[nt][1]),
                              "+f"(s[nt][2]), "+f"(s[nt][3])
                            : "r"(a0), "r"(a1), "r"(a2), "r"(a3),
                              "r"(b0), "r"(b1));
                    }
                }
            }
        }

        float alpha[2];
        __half* pw = sma + PW_OFF + w * 1280;
        #pragma unroll
        for (int i = 0; i < 2; i++) {
            int row = qbase + w * 16 + r0 + i * 8;
            float mx = -1e30f;
            #pragma unroll
            for (int nt = 0; nt < 4; nt++)
                #pragma unroll
                for (int j = 0; j < 2; j++) {
                    int key = kt * 32 + nt * 8 + (lane & 3) * 2 + j;
                    float sv = (key <= row)
                        ? s[nt][i * 2 + j] * 0.08838834764831845f : -1e30f;
                    s[nt][i * 2 + j] = sv;
                    mx = fmaxf(mx, sv);
                }
            mx = fmaxf(mx, __shfl_xor_sync(0xffffffffu, mx, 1));
            mx = fmaxf(mx, __shfl_xor_sync(0xffffffffu, mx, 2));
            float mnew = fmaxf(m[i], mx);
            alpha[i] = __expf(m[i] - mnew);
            m[i] = mnew;
            float psum = 0.f;
            #pragma unroll
            for (int nt = 0; nt < 4; nt++) {
                float p0 = __expf(s[nt][i * 2 + 0] - mnew);
                float p1 = __expf(s[nt][i * 2 + 1] - mnew);
                psum += p0 + p1;
                uint32_t hb, lb;
                split2(p0, p1, hb, lb);
                int po = (r0 + i * 8) * 40 + nt * 8 + (lane & 3) * 2;
                *(uint32_t*)(pw + po)       = hb;
                *(uint32_t*)(pw + 640 + po) = lb;
            }
            psum += __shfl_xor_sync(0xffffffffu, psum, 1);
            psum += __shfl_xor_sync(0xffffffffu, psum, 2);
            l[i] = l[i] * alpha[i] + psum;
            #pragma unroll
            for (int nt = 0; nt < 16; nt++) {
                acc_o[nt][i * 2 + 0] *= alpha[i];
                acc_o[nt][i * 2 + 1] *= alpha[i];
            }
        }
        __syncwarp();

        #pragma unroll
        for (int sl = 0; sl < 2; sl++) {
            #pragma unroll
            for (int ks = 0; ks < 2; ks++) {
                uint32_t a0, a1, a2, a3;
                {
                    int sub = lane >> 3;
                    int r = (lane & 7) + (sub & 1) * 8;
                    uint32_t addr = smb + (uint32_t)(PW_OFF + w * 1280 +
                        sl * 640 + r * 40 + ks * 16 + (sub >> 1) * 8) * 2;
                    asm volatile(
                        "ldmatrix.sync.aligned.m8n8.x4.shared.b16 "
                        "{%0,%1,%2,%3},[%4];"
                        : "=r"(a0), "=r"(a1), "=r"(a2), "=r"(a3) : "r"(addr));
                }
                #pragma unroll
                for (int nt = 0; nt < 16; nt++) {
                    uint32_t b0, b1;
                    int rr = nt * 8 + (lane & 7);
                    uint32_t addr = smb + (uint32_t)(VT_OFF + rr * 40 +
                        ks * 16 + ((lane >> 3) & 1) * 8) * 2;
                    asm volatile(
                        "ldmatrix.sync.aligned.m8n8.x2.shared.b16 {%0,%1},[%2];"
                        : "=r"(b0), "=r"(b1) : "r"(addr));
                    asm volatile(
                        "mma.sync.aligned.m16n8k16.row.col.f32.f16.f16.f32 "
                        "{%0,%1,%2,%3},{%4,%5,%6,%7},{%8,%9},{%0,%1,%2,%3};"
                        : "+f"(acc_o[nt][0]), "+f"(acc_o[nt][1]),
                          "+f"(acc_o[nt][2]), "+f"(acc_o[nt][3])
                        : "r"(a0), "r"(a1), "r"(a2), "r"(a3),
                          "r"(b0), "r"(b1));
                }
            }
        }
    }

    float inv[2] = { 1.f / l[0], 1.f / l[1] };
    #pragma unroll
    for (int nt = 0; nt < 16; nt++) {
        #pragma unroll
        for (int i = 0; i < 2; i++) {
            int row = qbase + w * 16 + r0 + i * 8;
            float v0 = acc_o[nt][i * 2 + 0] * inv[i];
            float v1 = acc_o[nt][i * 2 + 1] * inv[i];
            uint32_t hb, lb;
            split2(v0, v1, hb, lb);
            __half* o = ctxA + (size_t)row * 2 * HID + head * HD +
                        nt * 8 + (lane & 3) * 2;
            *(uint32_t*)(o)       = hb;
            *(uint32_t*)(o + HID) = lb;
        }
    }
}

// ---------------------------------------------------------------------------
// Host side
// ---------------------------------------------------------------------------
static void gemm(const __half* A2, const __half* B2,
                 const float* res, float* C, __half* Chalf,
                 int M, int N, int K, int SL, int mode) {
    dim3 grid(M / 128, N / 128);
    gemm_f16s<<<grid, 256, GEMM_SMEM>>>(A2, B2, res, C, Chalf, M, N, K, SL, mode);
}

static void split(const float* in, __half* out, int R, int K,
                  int rowmul = 1, int rowoff = 0) {
    int total4 = (int)(((size_t)R * K) >> 2);
    int kshift = (K == 2048) ? 9 : 11;
    split_kernel4<<<(total4 + 255) / 256, 256>>>(
        (const float4*)in, out, total4, kshift, K, rowmul, rowoff);
}

extern "C" void kernel_launch(void* const* d_in, const int* in_sizes, int n_in,
                              void* d_out, int out_size) {
    const float* hidden = (const float*)d_in[0];
    const int*   pos    = (const int*)d_in[2];
    const float* n1     = (const float*)d_in[3];
    const float* n2     = (const float*)d_in[4];
    const float* Wq     = (const float*)d_in[5];
    const float* Wk     = (const float*)d_in[6];
    const float* Wv     = (const float*)d_in[7];
    const float* Wo     = (const float*)d_in[8];
    const float* Wg     = (const float*)d_in[9];
    const float* Wu     = (const float*)d_in[10];
    const float* Wd     = (const float*)d_in[11];
    float* out = (float*)d_out;

    float* f = nullptr;
    __half* b = nullptr;
    cudaGetSymbolAddress((void**)&f, g_f32);
    cudaGetSymbolAddress((void**)&b, g_f16);

    float* qkv = f;
    float* x   = f + (size_t)6 * MEGAF;

    __half* hA    = b;
    __half* wqkvB = b + (size_t)8   * MEGAF;
    __half* ctxA  = b + (size_t)20  * MEGAF;
    __half* woB   = b + (size_t)28  * MEGAF;
    __half* h2A   = b + (size_t)36  * MEGAF;
    __half* guB   = b + (size_t)44  * MEGAF;   // interleaved gate/up rows
    __half* siluA = b + (size_t)108 * MEGAF;
    __half* wdB   = b + (size_t)140 * MEGAF;

    static bool attr_done = false;
    if (!attr_done) {
        cudaFuncSetAttribute(attn_tc_kernel,
                             cudaFuncAttributeMaxDynamicSharedMemorySize, ATTN_SMEM);
        cudaFuncSetAttribute(gemm_f16s,
                             cudaFuncAttributeMaxDynamicSharedMemorySize, GEMM_SMEM);
        attr_done = true;
    }

    // 1. RMSNorm 1 (fused hi/lo split)
    rmsnorm_split_kernel<<<SEQ, 256>>>(hidden, n1, hA);
    // 2. Split fused QKV weights: rows [Wq | Wk | Wv]
    split(Wq, wqkvB, 2048, HID);
    split(Wk, wqkvB + (size_t)2048 * 4096, 512, HID);
    split(Wv, wqkvB + (size_t)2560 * 4096, 512, HID);
    // 3. Fused QKV projection (3-slice)
    gemm(hA, wqkvB, nullptr, qkv, nullptr, SEQ, QKVN, HID, 3, 0);
    // 4. RoPE
    rope_kernel<<<(SEQ * NH * 64 + 255) / 256, 256>>>(qkv, NH, QKVN, 0, pos);
    rope_kernel<<<(SEQ * NKV * 64 + 255) / 256, 256>>>(qkv, NKV, QKVN, 2048, pos);
    // 5. Tensor-core attention
    attn_tc_kernel<<<dim3(32, NH), 128, ATTN_SMEM>>>(qkv, ctxA);
    // 6. O projection + residual (2-slice)
    split(Wo, woB, HID, HID);
    gemm(ctxA, woB, hidden, x, nullptr, SEQ, HID, HID, 2, 0);
    // 7. RMSNorm 2 (fused hi/lo split)
    rmsnorm_split_kernel<<<SEQ, 256>>>(x, n2, h2A);
    // 8. gate/up interleaved (2-slice) with fused SiLU epilogue -> siluA
    split(Wg, guB, INTER, HID, 2, 0);
    split(Wu, guB, INTER, HID, 2, 1);
    gemm(h2A, guB, nullptr, nullptr, siluA, SEQ, 2 * INTER, HID, 2, 1);
    // 9. Down projection + residual -> output (2-slice)
    split(Wd, wdB, HID, INTER);
    gemm(siluA, wdB, x, out, nullptr, SEQ, HID, INTER, 2, 0);
}